// round 11
// baseline (speedup 1.0000x reference)
#include <cuda_runtime.h>

// Fused 6-layer ReLU RNN + FC + log_softmax, diagonal-wavefront persistent kernel.
// R10: role-split lanes. Each (layer,neuron) is handled by TWO adjacent lanes:
//      role0 = Whh dot (+bias), role1 = Wih dot (x-proj for layer 0).
//      Each thread: 20 u64 weight regs only (~40 regs) -> 992 thr/CTA, 31 warps,
//      ~8 warps/SMSP (2x R6). Partials combined via shfl_xor(1) butterfly.
//      Grid=128 (one CTA/SM), plain __syncthreads() per tick (named bars are
//      2x slower on sm_103a - R8 evidence).

#define TT 1024
#define BB 2048
#define HH 20
#define LL 6
#define PP 8          // batch-pairs per CTA (pair = 2 batch elems packed f32x2)
#define PSTR 22       // padded h-row stride in 8B units (16B-aligned rows)
#define NTH 992
#define NCTA 128

typedef unsigned long long u64;

__device__ __forceinline__ u64 f2fma(u64 a, u64 b, u64 c) {
    u64 r; asm("fma.rn.f32x2 %0, %1, %2, %3;" : "=l"(r) : "l"(a), "l"(b), "l"(c)); return r;
}
__device__ __forceinline__ u64 f2add(u64 a, u64 b) {
    u64 r; asm("add.rn.f32x2 %0, %1, %2;" : "=l"(r) : "l"(a), "l"(b)); return r;
}
__device__ __forceinline__ u64 dup2(float x) {
    u64 r; asm("mov.b64 %0, {%1, %1};" : "=l"(r) : "f"(x)); return r;
}
__device__ __forceinline__ u64 pk2(float lo, float hi) {
    u64 r; asm("mov.b64 %0, {%1, %2};" : "=l"(r) : "f"(lo), "f"(hi)); return r;
}
__device__ __forceinline__ void unpk(u64 a, float& lo, float& hi) {
    asm("mov.b64 {%0, %1}, %2;" : "=f"(lo), "=f"(hi) : "l"(a));
}
// full-warp butterfly exchange of a u64 with lane^1
__device__ __forceinline__ u64 shflxor1(u64 v) {
    float lo, hi; unpk(v, lo, hi);
    lo = __shfl_xor_sync(0xffffffffu, lo, 1);
    hi = __shfl_xor_sync(0xffffffffu, hi, 1);
    return pk2(lo, hi);
}

// 20-element f32x2 dot product: weights from register array, h from SMEM.
__device__ __forceinline__ u64 dot20(const u64 (&w)[HH], const u64* hbase, u64 acc) {
    const ulonglong2* h = (const ulonglong2*)hbase;
    u64 a0 = acc, a1 = 0ull, a2 = 0ull, a3 = 0ull;
#pragma unroll
    for (int q = 0; q < 5; q++) {
        ulonglong2 h0 = h[q], h1 = h[q + 5];
        a0 = f2fma(w[2 * q],      h0.x, a0);
        a1 = f2fma(w[2 * q + 1],  h0.y, a1);
        a2 = f2fma(w[2 * q + 10], h1.x, a2);
        a3 = f2fma(w[2 * q + 11], h1.y, a3);
    }
    return f2add(f2add(a0, a1), f2add(a2, a3));
}

__global__ __launch_bounds__(NTH, 1) void rnn_wavefront_kernel(
    const float* __restrict__ x,     // [T, B, 2]
    const float* __restrict__ Wih0,  // [H, 2]
    const float* __restrict__ Wih,   // [L-1, H, H]
    const float* __restrict__ Whh,   // [L, H, H]
    const float* __restrict__ bih,   // [L, H]
    const float* __restrict__ bhh,   // [L, H]
    const float* __restrict__ fcw,   // [2, H]
    const float* __restrict__ fcb,   // [2]
    float* __restrict__ out)         // [T, B, 2]
{
    __shared__ __align__(16) u64 hb[2][LL][PP * PSTR];   // double-buffered h state
    __shared__ __align__(16) u64 logitb[2][PP][2];       // double-buffered logits

    const int tid = threadIdx.x;

    for (int i = tid; i < 2 * LL * PP * PSTR; i += NTH) ((u64*)hb)[i] = 0ull;
    for (int i = tid; i < 2 * PP * 2; i += NTH)         ((u64*)logitb)[i] = 0ull;

    // ---- role decomposition ----
    // layer lanes: tid = ((l*20 + j)*4 + pg)*2 + role   (0..959)
    //   warps are l-uniform (160 tids per layer = 5 warps exactly).
    const bool is_layer = tid < 960;
    const int l    = tid / 160;
    const int rem  = tid % 160;
    const int j    = rem >> 3;            // neuron 0..19
    const int pg   = (rem >> 1) & 3;      // pair-group 0..3
    const int role = tid & 1;             // 0 = Whh dot, 1 = Wih/x dot
    const int p0 = pg, p1 = pg + 4;       // two pairs per thread

    // fc lanes 960..975 (pair,class); softmax lanes 976..991 (pair,half)
    const bool is_fc = (tid >= 960) && (tid < 976);
    const int fc_p = (tid - 960) >> 1;
    const int fc_c = tid & 1;
    const int sm_p = (tid - 976) >> 1;
    const int sm_w = tid & 1;

    // ---- weights into registers (one 20-row per thread) ----
    u64 wh[HH];
    u64 bj = 0ull;
    u64 wx0 = 0ull, wx1 = 0ull;           // layer-0 input weights (role 1 only)
#pragma unroll
    for (int k = 0; k < HH; k++) wh[k] = 0ull;

    if (is_layer) {
        if (role == 0) {
#pragma unroll
            for (int k = 0; k < HH; k++) wh[k] = dup2(Whh[(l * HH + j) * HH + k]);
            bj = dup2(bih[l * HH + j] + bhh[l * HH + j]);
        } else if (l > 0) {
#pragma unroll
            for (int k = 0; k < HH; k++) wh[k] = dup2(Wih[((l - 1) * HH + j) * HH + k]);
        } else {
            // layer-0 input projection weights; wh stays zero (uniform dummy dot)
            wx0 = dup2(Wih0[j * 2 + 0]);
            wx1 = dup2(Wih0[j * 2 + 1]);
        }
    } else if (is_fc) {
#pragma unroll
        for (int k = 0; k < HH; k++) wh[k] = dup2(fcw[fc_c * HH + k]);
        bj = dup2(fcb[fc_c]);
    }

    // h source row: role0 reads own layer (t-1); role1 reads layer below (t).
    // layer-0 role1 reads its own layer as a harmless dummy (weights are zero).
    const int lsrc = (role == 0) ? l : (l > 0 ? l - 1 : 0);

    // ---- layer-0 input staging (role-1 threads of layer 0) ----
    const float2* __restrict__ x2 = (const float2*)x;   // x2[t*BB + b]
    float2 xa0, xb0, xa1, xb1;
    int b00 = 0, b01 = 0, b10 = 0, b11 = 0;
    const bool is_x = is_layer && (l == 0) && (role == 1);
    if (is_x) {
        b00 = blockIdx.x * PP + p0; b01 = b00 + (BB / 2);
        b10 = blockIdx.x * PP + p1; b11 = b10 + (BB / 2);
        xa0 = x2[b00]; xb0 = x2[b01];
        xa1 = x2[b10]; xb1 = x2[b11];
    }

    __syncthreads();

    for (int tau = 0; tau < TT + 7; ++tau) {
        const int A = tau & 1;
        const u64(*rb)[PP * PSTR] = hb[A];       // read buffer (last tick)
        u64(*wb)[PP * PSTR] = hb[A ^ 1];         // write buffer (this tick)

        if (is_layer) {
            const int t = tau - l;               // warp-uniform
            if ((unsigned)t < TT) {
                // uniform dot for both roles (role1-l0 has zero weights)
                u64 s0 = dot20(wh, &rb[lsrc][p0 * PSTR], bj);
                u64 s1 = dot20(wh, &rb[lsrc][p1 * PSTR], bj);
                if (is_x) {   // divergence confined to l0 warps, tiny branch
                    s0 = f2add(s0, f2add(f2fma(wx0, pk2(xa0.x, xb0.x), 0ull),
                                         f2fma(wx1, pk2(xa0.y, xb0.y), 0ull)));
                    s1 = f2add(s1, f2add(f2fma(wx0, pk2(xa1.x, xb1.x), 0ull),
                                         f2fma(wx1, pk2(xa1.y, xb1.y), 0ull)));
                }
                // combine with partner lane (wh-partial + wi-partial)
                u64 r0 = f2add(s0, shflxor1(s0));
                u64 r1 = f2add(s1, shflxor1(s1));
                if (role == 0) {
                    float lo, hi;
                    unpk(r0, lo, hi);
                    lo = fmaxf(lo, 0.0f); hi = fmaxf(hi, 0.0f);
                    *(float2*)&wb[l][p0 * PSTR + j] = make_float2(lo, hi);
                    unpk(r1, lo, hi);
                    lo = fmaxf(lo, 0.0f); hi = fmaxf(hi, 0.0f);
                    *(float2*)&wb[l][p1 * PSTR + j] = make_float2(lo, hi);
                }
            }
            // prefetch next x (layer-0 role-1 threads)
            if (is_x && tau + 1 < TT) {
                const int tn = tau + 1;
                xa0 = x2[tn * BB + b00]; xb0 = x2[tn * BB + b01];
                xa1 = x2[tn * BB + b10]; xb1 = x2[tn * BB + b11];
            }
        } else if (is_fc) {
            // ---- fc: logits(t = tau - 6), one (pair,class) per lane ----
            if ((unsigned)(tau - 6) < TT) {
                logitb[A ^ 1][fc_p][fc_c] = dot20(wh, &rb[5][fc_p * PSTR], bj);
            }
        } else {
            // ---- log_softmax + store, t = tau - 7 ----
            if ((unsigned)(tau - 7) < TT) {
                const int t = tau - 7;
                ulonglong2 lg = *(const ulonglong2*)&logitb[A][sm_p][0];
                float c0a, c0b, c1a, c1b;
                unpk(lg.x, c0a, c0b);   // class-0 logits for (b0, b1)
                unpk(lg.y, c1a, c1b);   // class-1 logits
                float u0 = sm_w ? c0b : c0a;
                float u1 = sm_w ? c1b : c1a;
                float m = fmaxf(u0, u1);
                float lse = m + __logf(1.0f + __expf(fminf(u0, u1) - m));
                const int pgl = blockIdx.x * PP + sm_p;
                const int b = sm_w ? pgl + (BB / 2) : pgl;
                *(float2*)&out[(size_t)(t * BB + b) * 2] = make_float2(u0 - lse, u1 - lse);
            }
        }

        __syncthreads();
    }
}

extern "C" void kernel_launch(void* const* d_in, const int* in_sizes, int n_in,
                              void* d_out, int out_size) {
    const float* x    = (const float*)d_in[0];
    const float* Wih0 = (const float*)d_in[1];
    const float* Wih  = (const float*)d_in[2];
    const float* Whh  = (const float*)d_in[3];
    const float* bih  = (const float*)d_in[4];
    const float* bhh  = (const float*)d_in[5];
    const float* fcw  = (const float*)d_in[6];
    const float* fcb  = (const float*)d_in[7];
    float* out = (float*)d_out;

    rnn_wavefront_kernel<<<NCTA, NTH>>>(x, Wih0, Wih, Whh, bih, bhh, fcw, fcb, out);
}

// round 12
// speedup vs baseline: 2.0083x; 2.0083x over previous
#include <cuda_runtime.h>

// Fused 6-layer ReLU RNN + FC + log_softmax, diagonal-wavefront persistent kernel.
// R12: role-split lanes (role0=Whh dot+bias, role1=Wih dot), 20 u64 weight regs
//      per thread. x is materialized as a virtual "layer -1" row in the h buffer
//      by 16 dedicated loader lanes, so ALL 960 layer lanes run one uniform
//      dot20 path (no x branch, no x staging registers -> no spills at 64 regs).
//      NTH=1024 (32 warps, 8/SMSP), grid=128, plain __syncthreads() per tick.

#define TT 1024
#define BB 2048
#define HH 20
#define LL 6
#define ROWS (LL + 1)  // row 0 = x, rows 1..6 = layers 0..5
#define PP 8           // batch-pairs per CTA (pair = 2 batch elems packed f32x2)
#define PSTR 22        // padded h-row stride in 8B units (16B-aligned rows)
#define NTH 1024
#define NCTA 128

typedef unsigned long long u64;

__device__ __forceinline__ u64 f2fma(u64 a, u64 b, u64 c) {
    u64 r; asm("fma.rn.f32x2 %0, %1, %2, %3;" : "=l"(r) : "l"(a), "l"(b), "l"(c)); return r;
}
__device__ __forceinline__ u64 f2add(u64 a, u64 b) {
    u64 r; asm("add.rn.f32x2 %0, %1, %2;" : "=l"(r) : "l"(a), "l"(b)); return r;
}
__device__ __forceinline__ u64 dup2(float x) {
    u64 r; asm("mov.b64 %0, {%1, %1};" : "=l"(r) : "f"(x)); return r;
}
__device__ __forceinline__ u64 pk2(float lo, float hi) {
    u64 r; asm("mov.b64 %0, {%1, %2};" : "=l"(r) : "f"(lo), "f"(hi)); return r;
}
__device__ __forceinline__ void unpk(u64 a, float& lo, float& hi) {
    asm("mov.b64 {%0, %1}, %2;" : "=f"(lo), "=f"(hi) : "l"(a));
}
// butterfly exchange of a u64 with lane^1
__device__ __forceinline__ u64 shflxor1(u64 v) {
    float lo, hi; unpk(v, lo, hi);
    lo = __shfl_xor_sync(0xffffffffu, lo, 1);
    hi = __shfl_xor_sync(0xffffffffu, hi, 1);
    return pk2(lo, hi);
}

// 20-element f32x2 dot product: weights from register array, h from SMEM.
__device__ __forceinline__ u64 dot20(const u64 (&w)[HH], const u64* hbase, u64 acc) {
    const ulonglong2* h = (const ulonglong2*)hbase;
    u64 a0 = acc, a1 = 0ull, a2 = 0ull, a3 = 0ull;
#pragma unroll
    for (int q = 0; q < 5; q++) {
        ulonglong2 h0 = h[q], h1 = h[q + 5];
        a0 = f2fma(w[2 * q],      h0.x, a0);
        a1 = f2fma(w[2 * q + 1],  h0.y, a1);
        a2 = f2fma(w[2 * q + 10], h1.x, a2);
        a3 = f2fma(w[2 * q + 11], h1.y, a3);
    }
    return f2add(f2add(a0, a1), f2add(a2, a3));
}

__global__ __launch_bounds__(NTH, 1) void rnn_wavefront_kernel(
    const float* __restrict__ x,     // [T, B, 2]
    const float* __restrict__ Wih0,  // [H, 2]
    const float* __restrict__ Wih,   // [L-1, H, H]
    const float* __restrict__ Whh,   // [L, H, H]
    const float* __restrict__ bih,   // [L, H]
    const float* __restrict__ bhh,   // [L, H]
    const float* __restrict__ fcw,   // [2, H]
    const float* __restrict__ fcb,   // [2]
    float* __restrict__ out)         // [T, B, 2]
{
    __shared__ __align__(16) u64 hb[2][ROWS][PP * PSTR];  // double-buffered x+h state
    __shared__ __align__(16) u64 logitb[2][PP][2];        // double-buffered logits

    const int tid = threadIdx.x;

    for (int i = tid; i < 2 * ROWS * PP * PSTR; i += NTH) ((u64*)hb)[i] = 0ull;
    for (int i = tid; i < 2 * PP * 2; i += NTH)           ((u64*)logitb)[i] = 0ull;

    // ---- role decomposition ----
    // layer lanes: tid = ((l*20 + j)*4 + pg)*2 + role   (0..959), l-uniform warps.
    const bool is_layer = tid < 960;
    const int l    = tid / 160;
    const int rem  = tid % 160;
    const int j    = rem >> 3;            // neuron 0..19
    const int pg   = (rem >> 1) & 3;      // pair-group 0..3
    const int role = tid & 1;             // 0 = Whh dot (+bias), 1 = Wih dot
    const int p0 = pg, p1 = pg + 4;       // two pairs per thread

    const bool is_fc = (tid >= 960) && (tid < 976);   // fc lanes (warp 30 lo)
    const bool is_sm = (tid >= 976) && (tid < 992);   // softmax lanes (warp 30 hi)
    const bool is_xl = (tid >= 992) && (tid < 1008);  // x-loader lanes (warp 31 lo)
    const int fc_p = (tid - 960) >> 1;
    const int fc_c = tid & 1;
    const int sm_p = (tid - 976) >> 1;
    const int sm_w = tid & 1;
    const int xl_p = (tid - 992) >> 1;    // pair for x loaders
    const int xl_k = tid & 1;             // input component 0/1

    // ---- weights into registers (one 20-row per thread) ----
    u64 wh[HH];
    u64 bj = 0ull;
#pragma unroll
    for (int k = 0; k < HH; k++) wh[k] = 0ull;

    if (is_layer) {
        if (role == 0) {
#pragma unroll
            for (int k = 0; k < HH; k++) wh[k] = dup2(Whh[(l * HH + j) * HH + k]);
            bj = dup2(bih[l * HH + j] + bhh[l * HH + j]);
        } else if (l > 0) {
#pragma unroll
            for (int k = 0; k < HH; k++) wh[k] = dup2(Wih[((l - 1) * HH + j) * HH + k]);
        } else {
            // layer 0 input weights occupy slots 0..1; rest stay zero so the
            // uniform dot20 over the x-row computes exactly wx0*x0 + wx1*x1.
            wh[0] = dup2(Wih0[j * 2 + 0]);
            wh[1] = dup2(Wih0[j * 2 + 1]);
        }
    } else if (is_fc) {
#pragma unroll
        for (int k = 0; k < HH; k++) wh[k] = dup2(fcw[fc_c * HH + k]);
        bj = dup2(fcb[fc_c]);
    }

    // dot source row: role0 reads own layer (row l+1, t-1); role1 reads row l
    // (layer below, or the x-row for l==0).
    const int lsrc = l + 1 - role;

    // ---- x-loader setup + initial x(0) fill ----
    const float* __restrict__ xf = (const float*)x;   // xf[(t*BB + b)*2 + k]
    int xb0 = 0, xb1 = 0;
    if (is_xl) {
        xb0 = blockIdx.x * PP + xl_p;
        xb1 = xb0 + (BB / 2);
        // pre-fill x(0) into buffer 0 (read at tau=0)
        hb[0][0][xl_p * PSTR + xl_k] = pk2(xf[xb0 * 2 + xl_k], xf[xb1 * 2 + xl_k]);
    }

    __syncthreads();

    for (int tau = 0; tau < TT + 7; ++tau) {
        const int A = tau & 1;
        const u64(*rb)[PP * PSTR] = hb[A];       // read buffer (last tick)
        u64(*wb)[PP * PSTR] = hb[A ^ 1];         // write buffer (this tick)

        if (is_layer) {
            const int t = tau - l;               // warp-uniform
            if ((unsigned)t < TT) {
                u64 s0 = dot20(wh, &rb[lsrc][p0 * PSTR], bj);
                u64 s1 = dot20(wh, &rb[lsrc][p1 * PSTR], bj);
                // combine wh-partial + wi-partial across adjacent role lanes
                u64 r0 = f2add(s0, shflxor1(s0));
                u64 r1 = f2add(s1, shflxor1(s1));
                if (role == 0) {
                    float lo, hi;
                    unpk(r0, lo, hi);
                    lo = fmaxf(lo, 0.0f); hi = fmaxf(hi, 0.0f);
                    *(float2*)&wb[l + 1][p0 * PSTR + j] = make_float2(lo, hi);
                    unpk(r1, lo, hi);
                    lo = fmaxf(lo, 0.0f); hi = fmaxf(hi, 0.0f);
                    *(float2*)&wb[l + 1][p1 * PSTR + j] = make_float2(lo, hi);
                }
            }
        } else if (is_xl) {
            // ---- write x(tau+1) into the write buffer's x-row ----
            const int tn = tau + 1;
            if (tn < TT) {
                const float v0 = xf[(tn * BB + xb0) * 2 + xl_k];
                const float v1 = xf[(tn * BB + xb1) * 2 + xl_k];
                wb[0][xl_p * PSTR + xl_k] = pk2(v0, v1);
            }
        } else if (is_fc) {
            // ---- fc: logits(t = tau - 6), one (pair,class) per lane ----
            if ((unsigned)(tau - 6) < TT) {
                logitb[A ^ 1][fc_p][fc_c] = dot20(wh, &rb[LL][fc_p * PSTR], bj);
            }
        } else if (is_sm) {
            // ---- log_softmax + store, t = tau - 7 ----
            if ((unsigned)(tau - 7) < TT) {
                const int t = tau - 7;
                ulonglong2 lg = *(const ulonglong2*)&logitb[A][sm_p][0];
                float c0a, c0b, c1a, c1b;
                unpk(lg.x, c0a, c0b);   // class-0 logits for (b0, b1)
                unpk(lg.y, c1a, c1b);   // class-1 logits
                float u0 = sm_w ? c0b : c0a;
                float u1 = sm_w ? c1b : c1a;
                float m = fmaxf(u0, u1);
                float lse = m + __logf(1.0f + __expf(fminf(u0, u1) - m));
                const int pgl = blockIdx.x * PP + sm_p;
                const int b = sm_w ? pgl + (BB / 2) : pgl;
                *(float2*)&out[(size_t)(t * BB + b) * 2] = make_float2(u0 - lse, u1 - lse);
            }
        }

        __syncthreads();
    }
}

extern "C" void kernel_launch(void* const* d_in, const int* in_sizes, int n_in,
                              void* d_out, int out_size) {
    const float* x    = (const float*)d_in[0];
    const float* Wih0 = (const float*)d_in[1];
    const float* Wih  = (const float*)d_in[2];
    const float* Whh  = (const float*)d_in[3];
    const float* bih  = (const float*)d_in[4];
    const float* bhh  = (const float*)d_in[5];
    const float* fcw  = (const float*)d_in[6];
    const float* fcb  = (const float*)d_in[7];
    float* out = (float*)d_out;

    rnn_wavefront_kernel<<<NCTA, NTH>>>(x, Wih0, Wih, Whh, bih, bhh, fcw, fcb, out);
}

// round 13
// speedup vs baseline: 4.9499x; 2.4647x over previous
#include <cuda_runtime.h>

// Fused 6-layer ReLU RNN + FC + log_softmax, diagonal-wavefront persistent kernel.
// R13: pipelined role-split. role1 computes wi(t)=Wih*h_{l-1}(t)+b at tick tau,
//      stages it in SMEM; role0 computes h_l(t)=relu(Whh*h_l(t-1)+staged) at
//      tick tau+1. Layer skew = 2 ticks. NO shuffles; role blocks are separate
//      warps with R6's broadcast-friendly lane layout (j fastest).
//      x = virtual row 0, register-prefetched 2 ticks ahead by softmax lanes.
//      NTH=992 (31 warps, ~8/SMSP), 64 regs (R12-proven), grid=128.

#define TT 1024
#define BB 2048
#define HH 20
#define LL 6
#define ROWS (LL + 1)  // row 0 = x, row l+1 = h_l
#define PP 8           // batch-pairs per CTA (pair = 2 batch elems packed f32x2)
#define PSTR 22        // padded row stride in 8B units (16B-aligned rows)
#define NTH 992
#define NCTA 128
#define NTICK (TT + 13)

typedef unsigned long long u64;

__device__ __forceinline__ u64 f2fma(u64 a, u64 b, u64 c) {
    u64 r; asm("fma.rn.f32x2 %0, %1, %2, %3;" : "=l"(r) : "l"(a), "l"(b), "l"(c)); return r;
}
__device__ __forceinline__ u64 f2add(u64 a, u64 b) {
    u64 r; asm("add.rn.f32x2 %0, %1, %2;" : "=l"(r) : "l"(a), "l"(b)); return r;
}
__device__ __forceinline__ u64 dup2(float x) {
    u64 r; asm("mov.b64 %0, {%1, %1};" : "=l"(r) : "f"(x)); return r;
}
__device__ __forceinline__ u64 pk2(float lo, float hi) {
    u64 r; asm("mov.b64 %0, {%1, %2};" : "=l"(r) : "f"(lo), "f"(hi)); return r;
}
__device__ __forceinline__ void unpk(u64 a, float& lo, float& hi) {
    asm("mov.b64 {%0, %1}, %2;" : "=f"(lo), "=f"(hi) : "l"(a));
}

// 20-element f32x2 dot: weights in registers, h in SMEM (broadcast-friendly).
__device__ __forceinline__ u64 dot20(const u64 (&w)[HH], const u64* hbase, u64 acc) {
    const ulonglong2* h = (const ulonglong2*)hbase;
    u64 a0 = acc, a1 = 0ull, a2 = 0ull, a3 = 0ull;
#pragma unroll
    for (int q = 0; q < 5; q++) {
        ulonglong2 h0 = h[q], h1 = h[q + 5];
        a0 = f2fma(w[2 * q],      h0.x, a0);
        a1 = f2fma(w[2 * q + 1],  h0.y, a1);
        a2 = f2fma(w[2 * q + 10], h1.x, a2);
        a3 = f2fma(w[2 * q + 11], h1.y, a3);
    }
    return f2add(f2add(a0, a1), f2add(a2, a3));
}

__global__ __launch_bounds__(NTH, 1) void rnn_wavefront_kernel(
    const float* __restrict__ x,     // [T, B, 2]
    const float* __restrict__ Wih0,  // [H, 2]
    const float* __restrict__ Wih,   // [L-1, H, H]
    const float* __restrict__ Whh,   // [L, H, H]
    const float* __restrict__ bih,   // [L, H]
    const float* __restrict__ bhh,   // [L, H]
    const float* __restrict__ fcw,   // [2, H]
    const float* __restrict__ fcb,   // [2]
    float* __restrict__ out)         // [T, B, 2]
{
    __shared__ __align__(16) u64 hb[2][ROWS][PP * PSTR];  // x + h state, double-buffered
    __shared__ __align__(16) u64 st[2][LL][PP * PSTR];    // staged wi partials
    __shared__ __align__(16) u64 logitb[2][PP][2];        // logits, double-buffered

    const int tid = threadIdx.x;

    for (int i = tid; i < 2 * ROWS * PP * PSTR; i += NTH) ((u64*)hb)[i] = 0ull;
    for (int i = tid; i < 2 * LL * PP * PSTR; i += NTH)   ((u64*)st)[i] = 0ull;
    for (int i = tid; i < 2 * PP * 2; i += NTH)           ((u64*)logitb)[i] = 0ull;

    // ---- role decomposition (role blocks -> role-uniform warps; within a
    //      block the layout is R6's: j fastest -> LDS broadcast pattern) ----
    const bool is_r0 = tid < 480;                       // Whh dot + relu + h store
    const bool is_r1 = (tid >= 480) && (tid < 960);     // Wih dot + stage
    const int rtid = is_r1 ? (tid - 480) : tid;
    const int l  = rtid / 80;
    const int rem = rtid % 80;
    const int j  = rem % 20;
    const int ph = rem / 20;             // 0..3
    const int p0 = ph, p1 = ph + 4;      // two pairs per thread

    const bool is_fc = (tid >= 960) && (tid < 976);     // warp 30 lo: fc
    const bool is_sm = (tid >= 976);                    // warp 30 hi: softmax + x-load
    const int fc_p = (tid - 960) >> 1;
    const int fc_c = tid & 1;
    const int sm_p = (tid - 976) >> 1;
    const int sm_w = tid & 1;

    // ---- weights into registers ----
    u64 wh[HH];
    u64 bj = 0ull;
#pragma unroll
    for (int k = 0; k < HH; k++) wh[k] = 0ull;

    if (is_r0) {
#pragma unroll
        for (int k = 0; k < HH; k++) wh[k] = dup2(Whh[(l * HH + j) * HH + k]);
    } else if (is_r1) {
        if (l > 0) {
#pragma unroll
            for (int k = 0; k < HH; k++) wh[k] = dup2(Wih[((l - 1) * HH + j) * HH + k]);
        } else {
            wh[0] = dup2(Wih0[j * 2 + 0]);   // x-row slots 2..19 stay zero
            wh[1] = dup2(Wih0[j * 2 + 1]);
        }
        bj = dup2(bih[l * HH + j] + bhh[l * HH + j]);   // bias rides the wi partial
    } else if (is_fc) {
#pragma unroll
        for (int k = 0; k < HH; k++) wh[k] = dup2(fcw[fc_c * HH + k]);
        bj = dup2(fcb[fc_c]);
    }

    // role source rows: role1 reads row l (h_{l-1} or x); role0 reads row l+1.
    const int lsrc = is_r0 ? (l + 1) : l;

    // ---- x prefetch state (sm lanes double as x loaders; 2-tick reg pipeline) ----
    const float* __restrict__ xf = (const float*)x;   // xf[(t*BB + b)*2 + k]
    int xb0 = 0, xb1 = 0;
    float xv0 = 0.0f, xv1 = 0.0f;        // x(tau+1) components held in regs
    if (is_sm) {
        xb0 = blockIdx.x * PP + sm_p;
        xb1 = xb0 + (BB / 2);
        // x(0) straight into read buffer 0; x(1) into regs
        hb[0][0][sm_p * PSTR + sm_w] = pk2(xf[xb0 * 2 + sm_w], xf[xb1 * 2 + sm_w]);
        if (TT > 1) {
            xv0 = xf[(BB + xb0) * 2 + sm_w];
            xv1 = xf[(BB + xb1) * 2 + sm_w];
        }
    }

    __syncthreads();

    for (int tau = 0; tau < NTICK; ++tau) {
        const int A = tau & 1;
        const u64(*rb)[PP * PSTR] = hb[A];       // read buffer (written last tick)
        u64(*wb)[PP * PSTR] = hb[A ^ 1];         // write buffer (this tick)
        const u64(*sr)[PP * PSTR] = st[A];       // staged partials (last tick)
        u64(*sw)[PP * PSTR] = st[A ^ 1];         // staged partials (this tick)

        if (is_r1) {
            // wi(t1) = Wih_l * h_{l-1}(t1) + b,  t1 = tau - 2l
            if ((unsigned)(tau - 2 * l) < TT) {
                sw[l][p0 * PSTR + j] = dot20(wh, &rb[lsrc][p0 * PSTR], bj);
                sw[l][p1 * PSTR + j] = dot20(wh, &rb[lsrc][p1 * PSTR], bj);
            }
        } else if (is_r0) {
            // h_l(t0) = relu(Whh_l * h_l(t0-1) + staged wi(t0)),  t0 = tau - 2l - 1
            if ((unsigned)(tau - 2 * l - 1) < TT) {
                u64 s0 = dot20(wh, &rb[lsrc][p0 * PSTR], sr[l][p0 * PSTR + j]);
                u64 s1 = dot20(wh, &rb[lsrc][p1 * PSTR], sr[l][p1 * PSTR + j]);
                float lo, hi;
                unpk(s0, lo, hi);
                lo = fmaxf(lo, 0.0f); hi = fmaxf(hi, 0.0f);
                *(float2*)&wb[l + 1][p0 * PSTR + j] = make_float2(lo, hi);
                unpk(s1, lo, hi);
                lo = fmaxf(lo, 0.0f); hi = fmaxf(hi, 0.0f);
                *(float2*)&wb[l + 1][p1 * PSTR + j] = make_float2(lo, hi);
            }
        } else if (is_fc) {
            // logits(t = tau - 12) from h_5 in row 6
            if ((unsigned)(tau - 12) < TT) {
                logitb[A ^ 1][fc_p][fc_c] = dot20(wh, &rb[LL][fc_p * PSTR], bj);
            }
        } else {
            // ---- x duty: stage x(tau+1) from regs, prefetch x(tau+2) ----
            const int t1 = tau + 1;
            if (t1 < TT) {
                wb[0][sm_p * PSTR + sm_w] = pk2(xv0, xv1);
            }
            const int t2 = tau + 2;
            if (t2 < TT) {
                xv0 = xf[(t2 * BB + xb0) * 2 + sm_w];
                xv1 = xf[(t2 * BB + xb1) * 2 + sm_w];
            }
            // ---- log_softmax + store, t = tau - 13 ----
            if ((unsigned)(tau - 13) < TT) {
                const int t = tau - 13;
                ulonglong2 lg = *(const ulonglong2*)&logitb[A][sm_p][0];
                float c0a, c0b, c1a, c1b;
                unpk(lg.x, c0a, c0b);   // class-0 logits for (b0, b1)
                unpk(lg.y, c1a, c1b);   // class-1 logits
                float u0 = sm_w ? c0b : c0a;
                float u1 = sm_w ? c1b : c1a;
                float m = fmaxf(u0, u1);
                float lse = m + __logf(1.0f + __expf(fminf(u0, u1) - m));
                const int b = sm_w ? xb1 : xb0;
                *(float2*)&out[(size_t)(t * BB + b) * 2] = make_float2(u0 - lse, u1 - lse);
            }
        }

        __syncthreads();
    }
}

extern "C" void kernel_launch(void* const* d_in, const int* in_sizes, int n_in,
                              void* d_out, int out_size) {
    const float* x    = (const float*)d_in[0];
    const float* Wih0 = (const float*)d_in[1];
    const float* Wih  = (const float*)d_in[2];
    const float* Whh  = (const float*)d_in[3];
    const float* bih  = (const float*)d_in[4];
    const float* bhh  = (const float*)d_in[5];
    const float* fcw  = (const float*)d_in[6];
    const float* fcb  = (const float*)d_in[7];
    float* out = (float*)d_out;

    rnn_wavefront_kernel<<<NCTA, NTH>>>(x, Wih0, Wih, Whh, bih, bhh, fcw, fcb, out);
}

// round 14
// speedup vs baseline: 6.1569x; 1.2438x over previous
#include <cuda_runtime.h>

// Fused 6-layer ReLU RNN + FC + log_softmax, diagonal-wavefront persistent kernel.
// R14: neuron-duo threads. Each layer thread owns neurons (j, j+10) of one layer
//      and 2 batch pairs: one h-row load feeds 40 FFMA2 (2x the FMA/LDS ratio of
//      R6 -> half the LDS.128 instructions). Role split (wh vs wi) keeps weights
//      at 40 u64 = 80 regs; wi partial staged in SMEM with 2-tick layer skew
//      (R13-validated) and consumed as the wh-dot accumulator init.
//      NTH=512 (16 warps, 128 regs), grid=128, plain __syncthreads() per tick.

#define TT 1024
#define BB 2048
#define HH 20
#define LL 6
#define ROWS (LL + 1)  // row 0 = x, row l+1 = h_l
#define PP 8           // batch-pairs per CTA (pair = 2 batch elems packed f32x2)
#define PSTR 22        // padded row stride in 8B units (16B-aligned rows)
#define NTH 512
#define NCTA 128
#define NTICK (TT + 13)

typedef unsigned long long u64;

__device__ __forceinline__ u64 f2fma(u64 a, u64 b, u64 c) {
    u64 r; asm("fma.rn.f32x2 %0, %1, %2, %3;" : "=l"(r) : "l"(a), "l"(b), "l"(c)); return r;
}
__device__ __forceinline__ u64 f2add(u64 a, u64 b) {
    u64 r; asm("add.rn.f32x2 %0, %1, %2;" : "=l"(r) : "l"(a), "l"(b)); return r;
}
__device__ __forceinline__ u64 dup2(float x) {
    u64 r; asm("mov.b64 %0, {%1, %1};" : "=l"(r) : "f"(x)); return r;
}
__device__ __forceinline__ u64 pk2(float lo, float hi) {
    u64 r; asm("mov.b64 %0, {%1, %2};" : "=l"(r) : "f"(lo), "f"(hi)); return r;
}
__device__ __forceinline__ void unpk(u64 a, float& lo, float& hi) {
    asm("mov.b64 {%0, %1}, %2;" : "=f"(lo), "=f"(hi) : "l"(a));
}

// Two 20-element f32x2 dots sharing one loaded h-row (neuron duo).
__device__ __forceinline__ void dot20x2(const u64 (&wa)[HH], const u64 (&wb_)[HH],
                                        const u64* hbase, u64 accA, u64 accB,
                                        u64& outA, u64& outB) {
    const ulonglong2* h2 = (const ulonglong2*)hbase;
    u64 aA0 = accA, aA1 = 0ull, aB0 = accB, aB1 = 0ull;
#pragma unroll
    for (int q = 0; q < 10; q++) {
        ulonglong2 hq = h2[q];
        aA0 = f2fma(wa[2 * q],     hq.x, aA0);
        aA1 = f2fma(wa[2 * q + 1], hq.y, aA1);
        aB0 = f2fma(wb_[2 * q],     hq.x, aB0);
        aB1 = f2fma(wb_[2 * q + 1], hq.y, aB1);
    }
    outA = f2add(aA0, aA1);
    outB = f2add(aB0, aB1);
}

// Single 20-element dot (fc lanes).
__device__ __forceinline__ u64 dot20(const u64 (&w)[HH], const u64* hbase, u64 acc) {
    const ulonglong2* h2 = (const ulonglong2*)hbase;
    u64 a0 = acc, a1 = 0ull;
#pragma unroll
    for (int q = 0; q < 10; q++) {
        ulonglong2 hq = h2[q];
        a0 = f2fma(w[2 * q],     hq.x, a0);
        a1 = f2fma(w[2 * q + 1], hq.y, a1);
    }
    return f2add(a0, a1);
}

__global__ __launch_bounds__(NTH, 1) void rnn_wavefront_kernel(
    const float* __restrict__ x,     // [T, B, 2]
    const float* __restrict__ Wih0,  // [H, 2]
    const float* __restrict__ Wih,   // [L-1, H, H]
    const float* __restrict__ Whh,   // [L, H, H]
    const float* __restrict__ bih,   // [L, H]
    const float* __restrict__ bhh,   // [L, H]
    const float* __restrict__ fcw,   // [2, H]
    const float* __restrict__ fcb,   // [2]
    float* __restrict__ out)         // [T, B, 2]
{
    __shared__ __align__(16) u64 hb[2][ROWS][PP * PSTR];  // x + h state, double-buffered
    __shared__ __align__(16) u64 st[2][LL][PP * HH];      // staged wi partials
    __shared__ __align__(16) u64 logitb[2][PP][2];        // logits, double-buffered

    const int tid = threadIdx.x;

    for (int i = tid; i < 2 * ROWS * PP * PSTR; i += NTH) ((u64*)hb)[i] = 0ull;
    for (int i = tid; i < 2 * LL * PP * HH; i += NTH)     ((u64*)st)[i] = 0ull;
    for (int i = tid; i < 2 * PP * 2; i += NTH)           ((u64*)logitb)[i] = 0ull;

    // ---- role decomposition (role-major: warps 0-6 wi... actually 0-7 / 7-14
    //      with exactly one mixed warp at the 240 boundary) ----
    // layer lanes: tid = role*240 + l*40 + pg*10 + jd   (0..479)
    const bool is_layer = tid < 480;
    const int role = tid / 240;          // 0 = wi-dot (stage), 1 = wh-dot (relu+store)
    const int sub  = tid % 240;
    const int l    = sub / 40;
    const int r2   = sub % 40;
    const int pg   = r2 / 10;            // pair-group 0..3
    const int jd   = r2 % 10;            // neuron duo: j = jd, j+10
    const int p0 = pg, p1 = pg + 4;

    const bool is_fc = (tid >= 480) && (tid < 496);     // fc lanes
    const bool is_sm = (tid >= 496);                    // softmax + x-loader lanes
    const int fc_p = (tid - 480) >> 1;
    const int fc_c = tid & 1;
    const int sm_p = (tid - 496) >> 1;
    const int sm_w = tid & 1;

    // ---- weights into registers: rows for neurons jd and jd+10 ----
    u64 wA[HH], wB[HH];
    u64 bjA = 0ull, bjB = 0ull;
#pragma unroll
    for (int k = 0; k < HH; k++) { wA[k] = 0ull; wB[k] = 0ull; }

    if (is_layer) {
        if (role == 1) {          // wh: recurrent weights
#pragma unroll
            for (int k = 0; k < HH; k++) {
                wA[k] = dup2(Whh[(l * HH + jd) * HH + k]);
                wB[k] = dup2(Whh[(l * HH + jd + 10) * HH + k]);
            }
        } else if (l > 0) {       // wi: input weights, generic layer
#pragma unroll
            for (int k = 0; k < HH; k++) {
                wA[k] = dup2(Wih[((l - 1) * HH + jd) * HH + k]);
                wB[k] = dup2(Wih[((l - 1) * HH + jd + 10) * HH + k]);
            }
            bjA = dup2(bih[l * HH + jd] + bhh[l * HH + jd]);
            bjB = dup2(bih[l * HH + jd + 10] + bhh[l * HH + jd + 10]);
        } else {                  // wi layer 0: x-projection in slots 0..1
            wA[0] = dup2(Wih0[jd * 2 + 0]);
            wA[1] = dup2(Wih0[jd * 2 + 1]);
            wB[0] = dup2(Wih0[(jd + 10) * 2 + 0]);
            wB[1] = dup2(Wih0[(jd + 10) * 2 + 1]);
            bjA = dup2(bih[jd] + bhh[jd]);
            bjB = dup2(bih[jd + 10] + bhh[jd + 10]);
        }
    } else if (is_fc) {
#pragma unroll
        for (int k = 0; k < HH; k++) wA[k] = dup2(fcw[fc_c * HH + k]);
        bjA = dup2(fcb[fc_c]);
    }

    // dot source rows: wi reads row l (h_{l-1} or x); wh reads row l+1 (h_l).
    const int lsrc = (role == 1) ? (l + 1) : l;

    // ---- x prefetch state (sm lanes; 2-tick register pipeline) ----
    const float* __restrict__ xf = (const float*)x;   // xf[(t*BB + b)*2 + k]
    int xb0 = 0, xb1 = 0;
    float xv0 = 0.0f, xv1 = 0.0f;
    if (is_sm) {
        xb0 = blockIdx.x * PP + sm_p;
        xb1 = xb0 + (BB / 2);
        hb[0][0][sm_p * PSTR + sm_w] = pk2(xf[xb0 * 2 + sm_w], xf[xb1 * 2 + sm_w]);
        xv0 = xf[(BB + xb0) * 2 + sm_w];
        xv1 = xf[(BB + xb1) * 2 + sm_w];
    }

    __syncthreads();

    for (int tau = 0; tau < NTICK; ++tau) {
        const int A = tau & 1;
        const u64(*rb)[PP * PSTR] = hb[A];       // read buffer (written last tick)
        u64(*wb)[PP * PSTR] = hb[A ^ 1];         // write buffer (this tick)
        const u64(*sr)[PP * HH] = st[A];         // staged wi (last tick)
        u64(*sw)[PP * HH] = st[A ^ 1];           // staged wi (this tick)

        if (is_layer) {
            if (role == 0) {
                // wi(t1) = Wih_l * h_{l-1}(t1) + b,  t1 = tau - 2l
                if ((unsigned)(tau - 2 * l) < TT) {
                    u64 oA, oB;
                    dot20x2(wA, wB, &rb[l][p0 * PSTR], bjA, bjB, oA, oB);
                    sw[l][p0 * HH + jd]      = oA;
                    sw[l][p0 * HH + jd + 10] = oB;
                    dot20x2(wA, wB, &rb[l][p1 * PSTR], bjA, bjB, oA, oB);
                    sw[l][p1 * HH + jd]      = oA;
                    sw[l][p1 * HH + jd + 10] = oB;
                }
            } else {
                // h_l(t0) = relu(Whh_l * h_l(t0-1) + staged wi(t0)), t0 = tau - 2l - 1
                if ((unsigned)(tau - 2 * l - 1) < TT) {
                    u64 oA, oB;
                    float lo, hi;
                    dot20x2(wA, wB, &rb[l + 1][p0 * PSTR],
                            sr[l][p0 * HH + jd], sr[l][p0 * HH + jd + 10], oA, oB);
                    unpk(oA, lo, hi);
                    wb[l + 1][p0 * PSTR + jd]      = pk2(fmaxf(lo, 0.0f), fmaxf(hi, 0.0f));
                    unpk(oB, lo, hi);
                    wb[l + 1][p0 * PSTR + jd + 10] = pk2(fmaxf(lo, 0.0f), fmaxf(hi, 0.0f));
                    dot20x2(wA, wB, &rb[l + 1][p1 * PSTR],
                            sr[l][p1 * HH + jd], sr[l][p1 * HH + jd + 10], oA, oB);
                    unpk(oA, lo, hi);
                    wb[l + 1][p1 * PSTR + jd]      = pk2(fmaxf(lo, 0.0f), fmaxf(hi, 0.0f));
                    unpk(oB, lo, hi);
                    wb[l + 1][p1 * PSTR + jd + 10] = pk2(fmaxf(lo, 0.0f), fmaxf(hi, 0.0f));
                }
            }
        } else if (is_fc) {
            // logits(t = tau - 12) from h_5 (row 6)
            if ((unsigned)(tau - 12) < TT) {
                logitb[A ^ 1][fc_p][fc_c] = dot20(wA, &rb[LL][fc_p * PSTR], bjA);
            }
        } else {
            // ---- x duty: stage x(tau+1) from regs, prefetch x(tau+2) ----
            if (tau + 1 < TT) {
                wb[0][sm_p * PSTR + sm_w] = pk2(xv0, xv1);
            }
            if (tau + 2 < TT) {
                xv0 = xf[((tau + 2) * BB + xb0) * 2 + sm_w];
                xv1 = xf[((tau + 2) * BB + xb1) * 2 + sm_w];
            }
            // ---- log_softmax + store, t = tau - 13 ----
            if ((unsigned)(tau - 13) < TT) {
                const int t = tau - 13;
                ulonglong2 lg = *(const ulonglong2*)&logitb[A][sm_p][0];
                float c0a, c0b, c1a, c1b;
                unpk(lg.x, c0a, c0b);   // class-0 logits for (b0, b1)
                unpk(lg.y, c1a, c1b);   // class-1 logits
                float u0 = sm_w ? c0b : c0a;
                float u1 = sm_w ? c1b : c1a;
                float m = fmaxf(u0, u1);
                float lse = m + __logf(1.0f + __expf(fminf(u0, u1) - m));
                const int b = sm_w ? xb1 : xb0;
                *(float2*)&out[(size_t)(t * BB + b) * 2] = make_float2(u0 - lse, u1 - lse);
            }
        }

        __syncthreads();
    }
}

extern "C" void kernel_launch(void* const* d_in, const int* in_sizes, int n_in,
                              void* d_out, int out_size) {
    const float* x    = (const float*)d_in[0];
    const float* Wih0 = (const float*)d_in[1];
    const float* Wih  = (const float*)d_in[2];
    const float* Whh  = (const float*)d_in[3];
    const float* bih  = (const float*)d_in[4];
    const float* bhh  = (const float*)d_in[5];
    const float* fcw  = (const float*)d_in[6];
    const float* fcb  = (const float*)d_in[7];
    float* out = (float*)d_out;

    rnn_wavefront_kernel<<<NCTA, NTH>>>(x, Wih0, Wih, Whh, bih, bhh, fcw, fcb, out);
}